// round 11
// baseline (speedup 1.0000x reference)
#include <cuda_runtime.h>
#include <cuda_bf16.h>

#define N_NODES 50000
#define N_EDGES 1600000
#define DIM 128
#define NODES_PER_BLOCK 64
#define THREADS 256

// CSR row offsets scratch (allocation-free: __device__ global)
__device__ int g_row_off[N_NODES + 1];

// packed f32x2 FMA: d += a*b (two fp32 lanes per instruction)
#define FFMA2(d, a, b) asm("fma.rn.f32x2 %0, %1, %2, %0;" : "+l"(d) : "l"(a), "l"(b))

__device__ __forceinline__ unsigned long long dup2(float v) {
    unsigned long long d;
    unsigned u = __float_as_uint(v);
    asm("mov.b64 %0, {%1, %1};" : "=l"(d) : "r"(u));
    return d;
}
__device__ __forceinline__ float lo32(unsigned long long v) {
    return __uint_as_float((unsigned)v);
}
__device__ __forceinline__ float hi32(unsigned long long v) {
    return __uint_as_float((unsigned)(v >> 32));
}

// ---------------- Kernel A: offsets via coalesced boundary scan ----------------
__global__ void scan_offsets_kernel(const int* __restrict__ dst) {
    int i = blockIdx.x * blockDim.x + threadIdx.x;
    if (i >= N_EDGES) return;
    const int d = dst[i];
    const int prev = (i == 0) ? -1 : dst[i - 1];
    for (int j = prev + 1; j <= d; j++) g_row_off[j] = i;
    if (i == N_EDGES - 1) {
        for (int j = d + 1; j <= N_NODES; j++) g_row_off[j] = N_EDGES;
    }
}

// ---------------- Kernel B: fused aggregate + warp-private f32x2 epilogue ----------------
// No __syncthreads: each warp aggregates its own 8 rows into its own smem slice,
// then immediately runs the GEMM epilogue for those rows. 32 KB smem + 64 regs
// -> 4 blocks/SM (32 warps) for latency coverage.
__global__ __launch_bounds__(THREADS, 4)
void gcn_fused_kernel(const float* __restrict__ H,
                      const int* __restrict__ esrc,
                      const float* __restrict__ ew,
                      const float* __restrict__ W,
                      const float* __restrict__ bias,
                      float* __restrict__ out)
{
    // per-warp 8-row slices, NON-duplicated floats. 32 KB.
    __shared__ float sAgg[NODES_PER_BLOCK][DIM];

    const int tid  = threadIdx.x;
    const int wid  = tid >> 5;
    const int lane = tid & 31;
    const int base = blockIdx.x * NODES_PER_BLOCK;

    const float4* __restrict__ H4 = (const float4*)H;

    // -------- Aggregation: warp handles its 8 consecutive nodes --------
    #pragma unroll 1
    for (int r = 0; r < NODES_PER_BLOCK / 8; r++) {
        const int rowLocal = wid * 8 + r;
        const int node = base + rowLocal;
        unsigned long long acc0 = 0ull, acc1 = 0ull;   // cols (4l,4l+1),(4l+2,4l+3)

        if (node < N_NODES) {
            const int s = g_row_off[node];
            const int e = g_row_off[node + 1];
            #pragma unroll 1
            for (int p = s; p < e; p += 32) {
                const int idx = p + lane;
                int   src = 0;
                float w   = 0.f;     // zero-pad: lanes past end contribute nothing
                if (idx < e) { src = esrc[idx]; w = ew[idx]; }
                const int cnt = min(32, e - p);
                if (cnt == 32) {
                    #pragma unroll
                    for (int g = 0; g < 32; g += 4) {
                        int   ss[4];
                        float ws[4];
                        #pragma unroll
                        for (int i = 0; i < 4; i++) {
                            ss[i] = __shfl_sync(0xffffffffu, src, g + i);
                            ws[i] = __shfl_sync(0xffffffffu, w,   g + i);
                        }
                        float4 hh[4];
                        #pragma unroll
                        for (int i = 0; i < 4; i++)
                            hh[i] = __ldcg(&H4[(size_t)ss[i] * 32 + lane]);  // L1-bypass
                        #pragma unroll
                        for (int i = 0; i < 4; i++) {
                            const unsigned long long wd = dup2(ws[i]);
                            ulonglong2 hp = *(const ulonglong2*)&hh[i];
                            FFMA2(acc0, wd, hp.x);
                            FFMA2(acc1, wd, hp.y);
                        }
                    }
                } else {
                    // partial strip: zero-padded 4-deep groups
                    #pragma unroll 1
                    for (int g = 0; g < cnt; g += 4) {
                        int   ss[4];
                        float ws[4];
                        #pragma unroll
                        for (int i = 0; i < 4; i++) {
                            ss[i] = __shfl_sync(0xffffffffu, src, g + i);
                            ws[i] = __shfl_sync(0xffffffffu, w,   g + i);
                        }
                        float4 hh[4];
                        #pragma unroll
                        for (int i = 0; i < 4; i++)
                            hh[i] = __ldcg(&H4[(size_t)ss[i] * 32 + lane]);
                        #pragma unroll
                        for (int i = 0; i < 4; i++) {
                            const unsigned long long wd = dup2(ws[i]);
                            ulonglong2 hp = *(const ulonglong2*)&hh[i];
                            FFMA2(acc0, wd, hp.x);
                            FFMA2(acc1, wd, hp.y);
                        }
                    }
                }
            }
        }
        // store 4 floats (16 B per lane), non-duplicated
        float4 st;
        st.x = lo32(acc0); st.y = hi32(acc0);
        st.z = lo32(acc1); st.w = hi32(acc1);
        *(float4*)&sAgg[rowLocal][4 * lane] = st;
    }

    __syncwarp();   // intra-warp smem visibility only; no block barrier

    // -------- f32x2 GEMM epilogue for THIS warp's 8 rows --------
    // lane tx owns cols 4tx..4tx+3 (2 packed pairs)
    const int tx = lane;
    const int ty = wid;
    unsigned long long c[8][2];
    #pragma unroll
    for (int i = 0; i < 8; i++) { c[i][0] = 0ull; c[i][1] = 0ull; }

    const unsigned long long* __restrict__ Wp = (const unsigned long long*)W;

    #pragma unroll 4
    for (int k = 0; k < DIM; k += 2) {
        // W rows k, k+1, this lane's 4 cols as 2 packed pairs each (L1-resident)
        const ulonglong2 w0 = *(const ulonglong2*)(Wp + (size_t)(k + 0) * 64 + tx * 2);
        const ulonglong2 w1 = *(const ulonglong2*)(Wp + (size_t)(k + 1) * 64 + tx * 2);
        #pragma unroll
        for (int i = 0; i < 8; i++) {
            const int r = ty * 8 + i;
            const float2 a = *(const float2*)&sAgg[r][k];   // broadcast LDS.64
            const unsigned long long ax = dup2(a.x);
            const unsigned long long ay = dup2(a.y);
            FFMA2(c[i][0], ax, w0.x); FFMA2(c[i][1], ax, w0.y);
            FFMA2(c[i][0], ay, w1.x); FFMA2(c[i][1], ay, w1.y);
        }
    }

    const float4 bb = ((const float4*)bias)[tx];
    #pragma unroll
    for (int i = 0; i < 8; i++) {
        const int row = base + ty * 8 + i;
        if (row < N_NODES) {
            float4 o;
            o.x = lo32(c[i][0]) + bb.x;
            o.y = hi32(c[i][0]) + bb.y;
            o.z = lo32(c[i][1]) + bb.z;
            o.w = hi32(c[i][1]) + bb.w;
            ((float4*)(out + (size_t)row * DIM))[tx] = o;
        }
    }
}

extern "C" void kernel_launch(void* const* d_in, const int* in_sizes, int n_in,
                              void* d_out, int out_size) {
    const float* H    = (const float*)d_in[0];
    const int*   esrc = (const int*)  d_in[1];
    const int*   edst = (const int*)  d_in[2];
    const float* ew   = (const float*)d_in[3];
    const float* W    = (const float*)d_in[4];
    const float* b    = (const float*)d_in[5];
    float* out = (float*)d_out;

    scan_offsets_kernel<<<(N_EDGES + 255) / 256, 256>>>(edst);

    const int nblocks = (N_NODES + NODES_PER_BLOCK - 1) / NODES_PER_BLOCK;
    gcn_fused_kernel<<<nblocks, THREADS>>>(H, esrc, ew, W, b, out);
}

// round 12
// speedup vs baseline: 1.4418x; 1.4418x over previous
#include <cuda_runtime.h>
#include <cuda_bf16.h>

#define N_NODES 50000
#define N_EDGES 1600000
#define DIM 128

// ---------------- scratch (allocation-free) ----------------
__device__ int   g_row_off[N_NODES + 1];
__device__ float g_agg[(size_t)N_NODES * DIM];   // aggregated features, 25.6 MB

// packed f32x2 FMA: d += a*b (two fp32 lanes per instruction)
#define FFMA2(d, a, b) asm("fma.rn.f32x2 %0, %1, %2, %0;" : "+l"(d) : "l"(a), "l"(b))

__device__ __forceinline__ unsigned long long dup2(float v) {
    unsigned long long d;
    unsigned u = __float_as_uint(v);
    asm("mov.b64 %0, {%1, %1};" : "=l"(d) : "r"(u));
    return d;
}
__device__ __forceinline__ float lo32(unsigned long long v) {
    return __uint_as_float((unsigned)v);
}
__device__ __forceinline__ float hi32(unsigned long long v) {
    return __uint_as_float((unsigned)(v >> 32));
}

// ---------------- Kernel A: offsets via coalesced boundary scan ----------------
__global__ void scan_offsets_kernel(const int* __restrict__ dst) {
    int i = blockIdx.x * blockDim.x + threadIdx.x;
    if (i >= N_EDGES) return;
    const int d = dst[i];
    const int prev = (i == 0) ? -1 : dst[i - 1];
    for (int j = prev + 1; j <= d; j++) g_row_off[j] = i;
    if (i == N_EDGES - 1) {
        for (int j = d + 1; j <= N_NODES; j++) g_row_off[j] = N_EDGES;
    }
}

// ---------------- Kernel B: pure gather-aggregate, warp-per-node ----------------
// No smem, no epilogue: maximal occupancy, all l1tex capacity for gathers.
__global__ __launch_bounds__(256)
void gather_kernel(const float* __restrict__ H,
                   const int* __restrict__ esrc,
                   const float* __restrict__ ew)
{
    const int lane = threadIdx.x & 31;
    const int node = blockIdx.x * 8 + (threadIdx.x >> 5);   // grid = 6250 -> node < 50000

    const int s = g_row_off[node];
    const int e = g_row_off[node + 1];

    const float4* __restrict__ H4 = (const float4*)H;
    unsigned long long acc0 = 0ull, acc1 = 0ull;            // cols (4l,4l+1),(4l+2,4l+3)

    #pragma unroll 1
    for (int p = s; p < e; p += 32) {
        const int idx = p + lane;
        int   src = 0;
        float w   = 0.f;                 // zero-pad: lanes past end contribute nothing
        if (idx < e) { src = esrc[idx]; w = ew[idx]; }
        const int cnt = min(32, e - p);
        if (cnt == 32) {
            #pragma unroll
            for (int g = 0; g < 32; g += 4) {
                int   ss[4];
                float ws[4];
                #pragma unroll
                for (int i = 0; i < 4; i++) {
                    ss[i] = __shfl_sync(0xffffffffu, src, g + i);
                    ws[i] = __shfl_sync(0xffffffffu, w,   g + i);
                }
                float4 hh[4];
                #pragma unroll
                for (int i = 0; i < 4; i++)
                    hh[i] = H4[(size_t)ss[i] * 32 + lane];
                #pragma unroll
                for (int i = 0; i < 4; i++) {
                    const unsigned long long wd = dup2(ws[i]);
                    ulonglong2 hp = *(const ulonglong2*)&hh[i];
                    FFMA2(acc0, wd, hp.x);
                    FFMA2(acc1, wd, hp.y);
                }
            }
        } else {
            // partial strip: zero-padded 4-deep groups
            #pragma unroll 1
            for (int g = 0; g < cnt; g += 4) {
                int   ss[4];
                float ws[4];
                #pragma unroll
                for (int i = 0; i < 4; i++) {
                    ss[i] = __shfl_sync(0xffffffffu, src, g + i);
                    ws[i] = __shfl_sync(0xffffffffu, w,   g + i);
                }
                float4 hh[4];
                #pragma unroll
                for (int i = 0; i < 4; i++)
                    hh[i] = H4[(size_t)ss[i] * 32 + lane];
                #pragma unroll
                for (int i = 0; i < 4; i++) {
                    const unsigned long long wd = dup2(ws[i]);
                    ulonglong2 hp = *(const ulonglong2*)&hh[i];
                    FFMA2(acc0, wd, hp.x);
                    FFMA2(acc1, wd, hp.y);
                }
            }
        }
    }

    float4 st;
    st.x = lo32(acc0); st.y = hi32(acc0);
    st.z = lo32(acc1); st.w = hi32(acc1);
    ((float4*)g_agg)[(size_t)node * 32 + lane] = st;
}

// ---------------- Kernel C: out = g_agg @ W + b  (f32x2, 64-row tiles) ----------------
// Staging duplicates each A scalar into (a,a) pairs so the epilogue is the proven
// R8 structure: broadcast LDS.128 feeding FFMA2 directly.
__global__ __launch_bounds__(256, 3)
void gemm_kernel(const float* __restrict__ W,
                 const float* __restrict__ bias,
                 float* __restrict__ out)
{
    __shared__ unsigned long long sA2[64][DIM];   // duplicated pairs, 64 KB

    const int tid  = threadIdx.x;
    const int wid  = tid >> 5;
    const int lane = tid & 31;
    const int base = blockIdx.x * 64;

    // stage A tile, duplicating scalars (coalesced float4 reads)
    const float4* __restrict__ A4 = (const float4*)g_agg;
    #pragma unroll
    for (int j = tid; j < 64 * 32; j += 256) {     // 2048 float4 slots
        const int row = j >> 5;
        const int c4  = j & 31;
        int gr = base + row;
        if (gr >= N_NODES) gr = N_NODES - 1;
        const float4 a = A4[(size_t)gr * 32 + c4];
        const int k = c4 << 2;
        sA2[row][k + 0] = dup2(a.x);
        sA2[row][k + 1] = dup2(a.y);
        sA2[row][k + 2] = dup2(a.z);
        sA2[row][k + 3] = dup2(a.w);
    }
    __syncthreads();

    // warp ty owns rows ty*8..ty*8+7; lane tx owns cols 4tx..4tx+3 (2 packed pairs)
    const int tx = lane;
    const int ty = wid;
    unsigned long long c[8][2];
    #pragma unroll
    for (int i = 0; i < 8; i++) { c[i][0] = 0ull; c[i][1] = 0ull; }

    const unsigned long long* __restrict__ Wp = (const unsigned long long*)W;

    #pragma unroll 4
    for (int k = 0; k < DIM; k += 2) {
        const ulonglong2 w0 = *(const ulonglong2*)(Wp + (size_t)(k + 0) * 64 + tx * 2);
        const ulonglong2 w1 = *(const ulonglong2*)(Wp + (size_t)(k + 1) * 64 + tx * 2);
        #pragma unroll
        for (int i = 0; i < 8; i++) {
            const int r = ty * 8 + i;
            const ulonglong2 A = *(const ulonglong2*)&sA2[r][k];   // dup(a_k), dup(a_k+1)
            FFMA2(c[i][0], A.x, w0.x); FFMA2(c[i][1], A.x, w0.y);
            FFMA2(c[i][0], A.y, w1.x); FFMA2(c[i][1], A.y, w1.y);
        }
    }

    const float4 bb = ((const float4*)bias)[tx];
    #pragma unroll
    for (int i = 0; i < 8; i++) {
        const int row = base + ty * 8 + i;
        if (row < N_NODES) {
            float4 o;
            o.x = lo32(c[i][0]) + bb.x;
            o.y = hi32(c[i][0]) + bb.y;
            o.z = lo32(c[i][1]) + bb.z;
            o.w = hi32(c[i][1]) + bb.w;
            ((float4*)(out + (size_t)row * DIM))[tx] = o;
        }
    }
}

extern "C" void kernel_launch(void* const* d_in, const int* in_sizes, int n_in,
                              void* d_out, int out_size) {
    const float* H    = (const float*)d_in[0];
    const int*   esrc = (const int*)  d_in[1];
    const int*   edst = (const int*)  d_in[2];
    const float* ew   = (const float*)d_in[3];
    const float* W    = (const float*)d_in[4];
    const float* b    = (const float*)d_in[5];
    float* out = (float*)d_out;

    scan_offsets_kernel<<<(N_EDGES + 255) / 256, 256>>>(edst);

    gather_kernel<<<N_NODES / 8, 256>>>(H, esrc, ew);    // 6250 blocks, warp per node

    gemm_kernel<<<(N_NODES + 63) / 64, 256>>>(W, b, out);
}

// round 13
// speedup vs baseline: 1.4830x; 1.0286x over previous
#include <cuda_runtime.h>
#include <cuda_fp16.h>

#define N_NODES 50000
#define N_EDGES 1600000
#define DIM 128

// ---------------- scratch (allocation-free) ----------------
__device__ int    g_row_off[N_NODES + 1];
__device__ __half g_Hh[(size_t)N_NODES * DIM];        // fp16 copy of H, 12.8 MB
__device__ float  g_agg[(size_t)N_NODES * DIM];       // aggregated features, 25.6 MB

// packed f32x2 FMA: d += a*b (two fp32 lanes per instruction)
#define FFMA2(d, a, b) asm("fma.rn.f32x2 %0, %1, %2, %0;" : "+l"(d) : "l"(a), "l"(b))

__device__ __forceinline__ unsigned long long dup2(float v) {
    unsigned long long d;
    unsigned u = __float_as_uint(v);
    asm("mov.b64 %0, {%1, %1};" : "=l"(d) : "r"(u));
    return d;
}
__device__ __forceinline__ unsigned long long pack2(float2 v) {
    unsigned long long d;
    asm("mov.b64 %0, {%1, %2};" : "=l"(d) : "r"(__float_as_uint(v.x)), "r"(__float_as_uint(v.y)));
    return d;
}
__device__ __forceinline__ float lo32(unsigned long long v) {
    return __uint_as_float((unsigned)v);
}
__device__ __forceinline__ float hi32(unsigned long long v) {
    return __uint_as_float((unsigned)(v >> 32));
}

// ---------------- Kernel A0: convert H -> fp16 (streaming, ~4 us) ----------------
__global__ void convert_kernel(const float* __restrict__ H) {
    const int i = blockIdx.x * blockDim.x + threadIdx.x;   // over N*DIM/4 float4s
    if (i >= N_NODES * DIM / 4) return;
    const float4 v = ((const float4*)H)[i];
    const __half2 h0 = __floats2half2_rn(v.x, v.y);
    const __half2 h1 = __floats2half2_rn(v.z, v.w);
    uint2 o;
    o.x = *(const unsigned*)&h0;
    o.y = *(const unsigned*)&h1;
    ((uint2*)g_Hh)[i] = o;
}

// ---------------- Kernel A: offsets via coalesced boundary scan (smem neighbor) ----------------
__global__ void scan_offsets_kernel(const int* __restrict__ dst) {
    __shared__ int sd[257];
    const int i = blockIdx.x * blockDim.x + threadIdx.x;
    const int t = threadIdx.x;
    int d = (i < N_EDGES) ? dst[i] : N_NODES;   // pad with sentinel
    sd[t + 1] = d;
    if (t == 0) sd[0] = (i == 0) ? -1 : dst[i - 1];
    __syncthreads();
    if (i >= N_EDGES) return;
    const int prev = sd[t];
    for (int j = prev + 1; j <= d; j++) g_row_off[j] = i;
    if (i == N_EDGES - 1) {
        for (int j = d + 1; j <= N_NODES; j++) g_row_off[j] = N_EDGES;
    }
}

// ---------------- Kernel B: pure gather-aggregate, warp-per-node, fp16 H ----------------
// L2 traffic halved: 256 B/row gathers (LDG.64 per lane), fp32 accumulation.
__global__ __launch_bounds__(256)
void gather_kernel(const int* __restrict__ esrc,
                   const float* __restrict__ ew)
{
    const int lane = threadIdx.x & 31;
    const int node = blockIdx.x * 8 + (threadIdx.x >> 5);   // grid = 6250 -> node < 50000

    const int s = g_row_off[node];
    const int e = g_row_off[node + 1];

    const uint2* __restrict__ Hh2 = (const uint2*)g_Hh;     // 4 halfs per lane per row
    unsigned long long acc0 = 0ull, acc1 = 0ull;            // cols (4l,4l+1),(4l+2,4l+3)

    #pragma unroll 1
    for (int p = s; p < e; p += 32) {
        const int idx = p + lane;
        int   src = 0;
        float w   = 0.f;                 // zero-pad: lanes past end contribute nothing
        if (idx < e) { src = esrc[idx]; w = ew[idx]; }
        const int cnt = min(32, e - p);
        if (cnt == 32) {
            #pragma unroll
            for (int g = 0; g < 32; g += 4) {
                int   ss[4];
                float ws[4];
                #pragma unroll
                for (int i = 0; i < 4; i++) {
                    ss[i] = __shfl_sync(0xffffffffu, src, g + i);
                    ws[i] = __shfl_sync(0xffffffffu, w,   g + i);
                }
                uint2 hv[4];
                #pragma unroll
                for (int i = 0; i < 4; i++)
                    hv[i] = Hh2[(size_t)ss[i] * 32 + lane];
                #pragma unroll
                for (int i = 0; i < 4; i++) {
                    const unsigned long long wd = dup2(ws[i]);
                    const float2 f01 = __half22float2(*(const __half2*)&hv[i].x);
                    const float2 f23 = __half22float2(*(const __half2*)&hv[i].y);
                    FFMA2(acc0, wd, pack2(f01));
                    FFMA2(acc1, wd, pack2(f23));
                }
            }
        } else {
            // partial strip: zero-padded 4-deep groups
            #pragma unroll 1
            for (int g = 0; g < cnt; g += 4) {
                int   ss[4];
                float ws[4];
                #pragma unroll
                for (int i = 0; i < 4; i++) {
                    ss[i] = __shfl_sync(0xffffffffu, src, g + i);
                    ws[i] = __shfl_sync(0xffffffffu, w,   g + i);
                }
                uint2 hv[4];
                #pragma unroll
                for (int i = 0; i < 4; i++)
                    hv[i] = Hh2[(size_t)ss[i] * 32 + lane];
                #pragma unroll
                for (int i = 0; i < 4; i++) {
                    const unsigned long long wd = dup2(ws[i]);
                    const float2 f01 = __half22float2(*(const __half2*)&hv[i].x);
                    const float2 f23 = __half22float2(*(const __half2*)&hv[i].y);
                    FFMA2(acc0, wd, pack2(f01));
                    FFMA2(acc1, wd, pack2(f23));
                }
            }
        }
    }

    float4 st;
    st.x = lo32(acc0); st.y = hi32(acc0);
    st.z = lo32(acc1); st.w = hi32(acc1);
    ((float4*)g_agg)[(size_t)node * 32 + lane] = st;
}

// ---------------- Kernel C: out = g_agg @ W + b  (f32x2, 64-row tiles) ----------------
__global__ __launch_bounds__(256, 3)
void gemm_kernel(const float* __restrict__ W,
                 const float* __restrict__ bias,
                 float* __restrict__ out)
{
    __shared__ unsigned long long sA2[64][DIM];   // duplicated pairs, 64 KB

    const int tid  = threadIdx.x;
    const int wid  = tid >> 5;
    const int lane = tid & 31;
    const int base = blockIdx.x * 64;

    // stage A tile, duplicating scalars (coalesced float4 reads)
    const float4* __restrict__ A4 = (const float4*)g_agg;
    #pragma unroll
    for (int j = tid; j < 64 * 32; j += 256) {     // 2048 float4 slots
        const int row = j >> 5;
        const int c4  = j & 31;
        int gr = base + row;
        if (gr >= N_NODES) gr = N_NODES - 1;
        const float4 a = A4[(size_t)gr * 32 + c4];
        const int k = c4 << 2;
        sA2[row][k + 0] = dup2(a.x);
        sA2[row][k + 1] = dup2(a.y);
        sA2[row][k + 2] = dup2(a.z);
        sA2[row][k + 3] = dup2(a.w);
    }
    __syncthreads();

    // warp ty owns rows ty*8..ty*8+7; lane tx owns cols 4tx..4tx+3 (2 packed pairs)
    const int tx = lane;
    const int ty = wid;
    unsigned long long c[8][2];
    #pragma unroll
    for (int i = 0; i < 8; i++) { c[i][0] = 0ull; c[i][1] = 0ull; }

    const unsigned long long* __restrict__ Wp = (const unsigned long long*)W;

    #pragma unroll 4
    for (int k = 0; k < DIM; k += 2) {
        const ulonglong2 w0 = *(const ulonglong2*)(Wp + (size_t)(k + 0) * 64 + tx * 2);
        const ulonglong2 w1 = *(const ulonglong2*)(Wp + (size_t)(k + 1) * 64 + tx * 2);
        #pragma unroll
        for (int i = 0; i < 8; i++) {
            const int r = ty * 8 + i;
            const ulonglong2 A = *(const ulonglong2*)&sA2[r][k];   // dup(a_k), dup(a_k+1)
            FFMA2(c[i][0], A.x, w0.x); FFMA2(c[i][1], A.x, w0.y);
            FFMA2(c[i][0], A.y, w1.x); FFMA2(c[i][1], A.y, w1.y);
        }
    }

    const float4 bb = ((const float4*)bias)[tx];
    #pragma unroll
    for (int i = 0; i < 8; i++) {
        const int row = base + ty * 8 + i;
        if (row < N_NODES) {
            float4 o;
            o.x = lo32(c[i][0]) + bb.x;
            o.y = hi32(c[i][0]) + bb.y;
            o.z = lo32(c[i][1]) + bb.z;
            o.w = hi32(c[i][1]) + bb.w;
            ((float4*)(out + (size_t)row * DIM))[tx] = o;
        }
    }
}

extern "C" void kernel_launch(void* const* d_in, const int* in_sizes, int n_in,
                              void* d_out, int out_size) {
    const float* H    = (const float*)d_in[0];
    const int*   esrc = (const int*)  d_in[1];
    const int*   edst = (const int*)  d_in[2];
    const float* ew   = (const float*)d_in[3];
    const float* W    = (const float*)d_in[4];
    const float* b    = (const float*)d_in[5];
    float* out = (float*)d_out;

    convert_kernel<<<(N_NODES * DIM / 4 + 255) / 256, 256>>>(H);

    scan_offsets_kernel<<<(N_EDGES + 255) / 256, 256>>>(edst);

    gather_kernel<<<N_NODES / 8, 256>>>(esrc, ew);    // 6250 blocks, warp per node

    gemm_kernel<<<(N_NODES + 63) / 64, 256>>>(W, b, out);
}